// round 3
// baseline (speedup 1.0000x reference)
#include <cuda_runtime.h>
#include <cuda_fp16.h>

// Problem constants
#define HD   160            // H = W = D = 160
#define PLN  25600          // W*D
#define VOL  4096000        // H*W*D
#define NVOX 8192000ULL     // B*C*H*W*D = 2*160^3
#define WT   20             // w-tile width in pass A (outputs per block)
#define ROWS 30             // WT + 2*5 halo
#define SP   170            // padded smem row length (160 + 2*5)
#define HSEG 40             // h-segment length in pass B

// Normalized 1D Gaussian, KS=11, sigma=1.5 (symmetric), compile-time constants
__device__ constexpr float GW[11] = {
    0.00102838f, 0.00759876f, 0.03600077f, 0.10936070f, 0.21300553f,
    0.26601172f,
    0.21300553f, 0.10936070f, 0.03600077f, 0.00759876f, 0.00102838f
};

constexpr float C1f  = 1.0e-4f;
constexpr float C2f  = 9.0e-4f;
constexpr float EPSf = 1.0e-12f;

// Scratch: 5 blurred fields (mu1, mu2, m11, m22, m12) in fp16, each NVOX.
__device__ __half gh_buf[5ULL * NVOX];
__device__ double g_acc;

__device__ __forceinline__ int refl(int i) {
    return (i < 0) ? -i : ((i > HD - 1) ? (2 * (HD - 1) - i) : i);
}

// ---------------------------------------------------------------------------
// Pass A: per (b, h, w-tile): load s,r rows [w0-5, w0+WT+5) x D(padded) into
// SMEM, then per row: D-blur (5 fields) into an 11-deep register ring; once
// the ring is full, emit the W-blurred output directly from registers.
// Block: 160 threads, tid = d. Smem: 2 * ROWS * SP floats = 40.8 KB.
// ---------------------------------------------------------------------------
__global__ void __launch_bounds__(HD) passA(const float* __restrict__ src,
                                            const float* __restrict__ ref) {
    __shared__ float S[ROWS * SP];
    __shared__ float R[ROWS * SP];

    const int d  = threadIdx.x;
    const int b  = blockIdx.z;
    const int h  = blockIdx.y;
    const int w0 = blockIdx.x * WT;

    const size_t basebh = ((size_t)(b * HD + h)) * PLN;

    // Load ROWS w-lines (reflect in w), padded+reflected in d.
    #pragma unroll
    for (int row = 0; row < ROWS; ++row) {
        const int w = refl(w0 - 5 + row);
        const float* ps = src + basebh + (size_t)w * HD;
        const float* pr = ref + basebh + (size_t)w * HD;
        S[row * SP + 5 + d] = __ldg(ps + d);
        R[row * SP + 5 + d] = __ldg(pr + d);
        if (d < 5) {                       // left halo: j=d -> global 5-d
            S[row * SP + d] = __ldg(ps + (5 - d));
            R[row * SP + d] = __ldg(pr + (5 - d));
        }
        if (d >= 155) {                    // right halo: j=d+10 -> global 313-d
            S[row * SP + d + 10] = __ldg(ps + (313 - d));
            R[row * SP + d + 10] = __ldg(pr + (313 - d));
        }
    }
    __syncthreads();

    // Register ring of D-blurred values, 5 fields x 11 rows.
    float q0[11], q1[11], q2[11], q3[11], q4[11];

    #pragma unroll
    for (int r = 0; r < ROWS; ++r) {
        float a0 = 0.f, a1 = 0.f, a2 = 0.f, a3 = 0.f, a4 = 0.f;
        #pragma unroll
        for (int k = 0; k < 11; ++k) {
            float s = S[r * SP + d + k];
            float v = R[r * SP + d + k];
            float t = GW[k] * s;
            float u = GW[k] * v;
            a0 += t; a1 += u; a2 += t * s; a3 += u * v; a4 += t * v;
        }
        const int sl = r % 11;
        q0[sl] = a0; q1[sl] = a1; q2[sl] = a2; q3[sl] = a3; q4[sl] = a4;

        if (r >= 10) {
            float m0 = 0.f, m1 = 0.f, m2 = 0.f, m3 = 0.f, m4 = 0.f;
            #pragma unroll
            for (int k = 0; k < 11; ++k) {
                const int s2 = (r - 10 + k) % 11;
                m0 += GW[k] * q0[s2];
                m1 += GW[k] * q1[s2];
                m2 += GW[k] * q2[s2];
                m3 += GW[k] * q3[s2];
                m4 += GW[k] * q4[s2];
            }
            const size_t off = basebh + (size_t)(w0 + r - 10) * HD + d;
            gh_buf[0ULL * NVOX + off] = __float2half_rn(m0);
            gh_buf[1ULL * NVOX + off] = __float2half_rn(m1);
            gh_buf[2ULL * NVOX + off] = __float2half_rn(m2);
            gh_buf[3ULL * NVOX + off] = __float2half_rn(m3);
            gh_buf[4ULL * NVOX + off] = __float2half_rn(m4);
        }
    }
}

// ---------------------------------------------------------------------------
// Pass B: H-blur via 11-plane register ring over fp16 scratch, SSIM + reduce.
// Block: 160 threads (tid = d), grid (HD/HSEG, W, B).
// ---------------------------------------------------------------------------
__global__ void __launch_bounds__(HD) passB() {
    const int d  = threadIdx.x;
    const int b  = blockIdx.z;
    const int w  = blockIdx.y;
    const int h0 = blockIdx.x * HSEG;

    const size_t colbase = (size_t)b * VOL + (size_t)w * HD + d;

    const __half* __restrict__ F0 = gh_buf + 0ULL * NVOX;
    const __half* __restrict__ F1 = gh_buf + 1ULL * NVOX;
    const __half* __restrict__ F2 = gh_buf + 2ULL * NVOX;
    const __half* __restrict__ F3 = gh_buf + 3ULL * NVOX;
    const __half* __restrict__ F4 = gh_buf + 4ULL * NVOX;

    float win[5][11];

    // Warm-up: planes h0-5 .. h0+4 into slots 0..9.
    #pragma unroll
    for (int j = 0; j < 10; ++j) {
        const int q = refl(h0 - 5 + j);
        const size_t off = colbase + (size_t)q * PLN;
        win[0][j] = __half2float(__ldg(F0 + off));
        win[1][j] = __half2float(__ldg(F1 + off));
        win[2][j] = __half2float(__ldg(F2 + off));
        win[3][j] = __half2float(__ldg(F3 + off));
        win[4][j] = __half2float(__ldg(F4 + off));
    }

    float acc = 0.f;

    #pragma unroll
    for (int i = 0; i < HSEG; ++i) {
        {
            const int q = refl(h0 + i + 5);
            const size_t off = colbase + (size_t)q * PLN;
            const int slot = (i + 10) % 11;
            win[0][slot] = __half2float(__ldg(F0 + off));
            win[1][slot] = __half2float(__ldg(F1 + off));
            win[2][slot] = __half2float(__ldg(F2 + off));
            win[3][slot] = __half2float(__ldg(F3 + off));
            win[4][slot] = __half2float(__ldg(F4 + off));
        }
        float mu1 = 0.f, mu2 = 0.f, m11 = 0.f, m22 = 0.f, m12 = 0.f;
        #pragma unroll
        for (int k = 0; k < 11; ++k) {
            const int slot = (i + k) % 11;
            mu1 += GW[k] * win[0][slot];
            mu2 += GW[k] * win[1][slot];
            m11 += GW[k] * win[2][slot];
            m22 += GW[k] * win[3][slot];
            m12 += GW[k] * win[4][slot];
        }
        const float mu1sq = mu1 * mu1;
        const float mu2sq = mu2 * mu2;
        const float mu12  = mu1 * mu2;
        const float s1  = m11 - mu1sq;
        const float s2  = m22 - mu2sq;
        const float s12 = m12 - mu12;
        const float num = (2.f * mu12 + C1f) * (2.f * s12 + C2f);
        const float den = (mu1sq + mu2sq + C1f) * (s1 + s2 + C2f);
        acc += num / (den + EPSf);
    }

    // Reduce: 5 warps -> smem -> atomicAdd(double)
    float v = acc;
    #pragma unroll
    for (int o = 16; o > 0; o >>= 1) v += __shfl_down_sync(0xffffffffu, v, o);
    __shared__ float ws[5];
    if ((threadIdx.x & 31) == 0) ws[threadIdx.x >> 5] = v;
    __syncthreads();
    if (threadIdx.x == 0) {
        float s = ws[0] + ws[1] + ws[2] + ws[3] + ws[4];
        atomicAdd(&g_acc, (double)s);
    }
}

__global__ void zero_acc_kernel() { g_acc = 0.0; }

__global__ void finalize_kernel(float* out) {
    out[0] = (float)(1.0 - g_acc / (double)NVOX);
}

extern "C" void kernel_launch(void* const* d_in, const int* in_sizes, int n_in,
                              void* d_out, int out_size) {
    const float* src = (const float*)d_in[0];
    const float* ref = (const float*)d_in[1];
    float* out = (float*)d_out;

    zero_acc_kernel<<<1, 1>>>();
    passA<<<dim3(HD / WT, HD, 2), HD>>>(src, ref);
    passB<<<dim3(HD / HSEG, HD, 2), HD>>>();
    finalize_kernel<<<1, 1>>>(out);
}